// round 15
// baseline (speedup 1.0000x reference)
#include <cuda_runtime.h>
#include <cuda_bf16.h>
#include <cuda_fp16.h>
#include <cstdint>

// Problem constants
#define B_ 4
#define S_ 1024
#define D_ 1024
#define H_ 16
#define DK_ 64
#define M_TOT (B_ * S_)   // 4096

// Q/K/V in fp16, head-major: [(b*H+h)][s][64], 64-elem rows (128B).
// Q is pre-scaled by 0.125*log2(e).
__device__ uint16_t g_Q16[B_ * H_ * S_ * DK_];
__device__ uint16_t g_K16[B_ * H_ * S_ * DK_];
__device__ uint16_t g_V16[B_ * H_ * S_ * DK_];
// fp16-pre-converted projection inputs
__device__ uint16_t g_X16[3 * M_TOT * D_];
__device__ uint16_t g_W16[3 * D_ * D_];
// per-64-column-block mask validity flags: [b][blk] (1 = all 64 cols valid)
__device__ int g_mflag[B_ * (S_ / 64)];

#define SCL_Q 0.18033688011112042f   // 0.125 * log2(e)

// ---------------------------------------------------------------------------
// PTX helpers (baseline sm_80+ features only — target is sm_100 BASE).
// ---------------------------------------------------------------------------
__device__ __forceinline__ void cp_async16(void* smem_dst, const void* gmem_src) {
    uint32_t d = (uint32_t)__cvta_generic_to_shared(smem_dst);
    asm volatile("cp.async.ca.shared.global [%0], [%1], 16;"
                 :: "r"(d), "l"(gmem_src) : "memory");
}
#define CP_ASYNC_COMMIT() asm volatile("cp.async.commit_group;" ::: "memory")
#define CP_ASYNC_WAIT1()  asm volatile("cp.async.wait_group 1;" ::: "memory")
#define CP_ASYNC_WAIT3()  asm volatile("cp.async.wait_group 3;" ::: "memory")

// fp16 m16n8k16, fp32 accumulate
__device__ __forceinline__ void mma_f16(float c[4],
                                        uint32_t a0, uint32_t a1, uint32_t a2, uint32_t a3,
                                        uint32_t b0, uint32_t b1) {
    asm volatile(
        "mma.sync.aligned.m16n8k16.row.col.f32.f16.f16.f32 "
        "{%0,%1,%2,%3}, {%4,%5,%6,%7}, {%8,%9}, {%0,%1,%2,%3};"
        : "+f"(c[0]), "+f"(c[1]), "+f"(c[2]), "+f"(c[3])
        : "r"(a0), "r"(a1), "r"(a2), "r"(a3), "r"(b0), "r"(b1));
}
__device__ __forceinline__ void ldmatrix_x4(uint32_t& r0, uint32_t& r1,
                                            uint32_t& r2, uint32_t& r3,
                                            uint32_t smem_addr) {
    asm volatile("ldmatrix.sync.aligned.m8n8.x4.shared.b16 "
                 "{%0,%1,%2,%3}, [%4];"
                 : "=r"(r0), "=r"(r1), "=r"(r2), "=r"(r3) : "r"(smem_addr));
}
__device__ __forceinline__ void ldmatrix_x4_trans(uint32_t& r0, uint32_t& r1,
                                                  uint32_t& r2, uint32_t& r3,
                                                  uint32_t smem_addr) {
    asm volatile("ldmatrix.sync.aligned.m8n8.x4.trans.shared.b16 "
                 "{%0,%1,%2,%3}, [%4];"
                 : "=r"(r0), "=r"(r1), "=r"(r2), "=r"(r3) : "r"(smem_addr));
}
__device__ __forceinline__ uint32_t packhf(float a, float b) {
    __half2 t = __floats2half2_rn(a, b);
    return *reinterpret_cast<uint32_t*>(&t);
}

// head-major index for proj epilogue stores
#define QKV_IDX(row, col) \
    ((((size_t)((row) >> 10) * H_ + ((col) >> 6)) << 16) + \
     (((size_t)((row) & 1023)) << 6) + ((col) & 63))

// ---------------------------------------------------------------------------
// Pre-pass: fp32 -> fp16, float4-vectorized, z picks tensor.
// ---------------------------------------------------------------------------
__global__ void cvt_f16_kernel(const float* __restrict__ a,
                               const float* __restrict__ b,
                               const float* __restrict__ c,
                               uint16_t* __restrict__ out, int n4) {
    int i = blockIdx.x * blockDim.x + threadIdx.x;
    if (i >= n4) return;
    const float* src = (blockIdx.z == 0) ? a : (blockIdx.z == 1) ? b : c;
    float4 v = ((const float4*)src)[i];
    uint2 r;
    r.x = packhf(v.x, v.y);
    r.y = packhf(v.z, v.w);
    ((uint2*)(out + (size_t)blockIdx.z * n4 * 4))[i] = r;
}

// ---------------------------------------------------------------------------
// Pre-pass: mask -> per-64-col-block validity flag. One thread per block.
// ---------------------------------------------------------------------------
__global__ void mask_flags_kernel(const int* __restrict__ mask) {
    int i = threadIdx.x;                 // 0..63  -> (b, blk)
    if (i >= B_ * (S_ / 64)) return;
    const int* m = mask + (i >> 4) * S_ + (i & 15) * 64;
    int all = 1;
    #pragma unroll 8
    for (int j = 0; j < 64; j++) all &= (m[j] != 0);
    g_mflag[i] = all;
}

// ---------------------------------------------------------------------------
// Projection GEMM via fp16 m16n8k16. 4-stage cp.async ring, PBK=32
// (prefetch distance 3 -> up to 60KB in flight per CTA).
// Epilogue emits fp16 head-major; Q output pre-scaled by SCL_Q.
// ---------------------------------------------------------------------------
#define PBM 128
#define PBN 128
#define PBK 32
#define PROW 40                     // ushort row stride (80B) — conflict-free
#define PSTAGES 4
#define KSTEPS (D_ / PBK)           // 32
#define P_A_USH (PBM * PROW)        // 5120 ushorts per A tile
#define P_STG_USH (2 * P_A_USH)     // A then B per stage
#define PROJ_SMEM (PSTAGES * P_STG_USH * 2)   // 81920 B

__global__ __launch_bounds__(256, 2)
void qkv_proj_mma(const float* __restrict__ bq,
                  const float* __restrict__ bk,
                  const float* __restrict__ bv) {
    extern __shared__ uint16_t psm[];

    const int z = blockIdx.z;
    const uint16_t* X = g_X16 + (size_t)z * M_TOT * D_;
    const uint16_t* W = g_W16 + (size_t)z * D_ * D_;
    const float* bias = (z == 0) ? bq : (z == 1) ? bk : bv;
    uint16_t* Out = (z == 0) ? g_Q16 : (z == 1) ? g_K16 : g_V16;
    const float oscale = (z == 0) ? SCL_Q : 1.0f;

    const int t   = threadIdx.x;
    const int wid = t >> 5;
    const int lid = t & 31;
    const int lr  = lid >> 2;
    const int lc  = lid & 3;
    const int wm  = wid & 1;
    const int wn  = wid >> 1;
    const int m0  = blockIdx.y * PBM;
    const int n0  = blockIdx.x * PBN;

    const int lrow8 = (lid & 7) + (lid & 8);          // 0..15
    const int lcol8 = (lid >> 4) << 3;                // 0 or 8

    float acc[4][4][4];
    #pragma unroll
    for (int i = 0; i < 4; i++)
        #pragma unroll
        for (int j = 0; j < 4; j++)
            #pragma unroll
            for (int r = 0; r < 4; r++) acc[i][j][r] = 0.f;

    auto load_stage = [&](int st, int ks) {
        const int k0 = ks * PBK;
        uint16_t* A  = psm + st * P_STG_USH;
        uint16_t* Bm = A + P_A_USH;
        #pragma unroll
        for (int i = 0; i < 2; i++) {
            int job = t + i * 256;          // 0..511
            int row = job >> 2;             // 0..127
            int ch  = (job & 3) * 8;        // ushort offset 0,8,16,24
            cp_async16(&A[row * PROW + ch],  &X[(size_t)(m0 + row) * D_ + k0 + ch]);
            cp_async16(&Bm[row * PROW + ch], &W[(size_t)(n0 + row) * D_ + k0 + ch]);
        }
    };

    load_stage(0, 0); CP_ASYNC_COMMIT();
    load_stage(1, 1); CP_ASYNC_COMMIT();
    load_stage(2, 2); CP_ASYNC_COMMIT();

    int st = 0;
    for (int ks = 0; ks < KSTEPS; ks++) {
        if (ks + 3 < KSTEPS) {
            int nst = st + 3; if (nst >= PSTAGES) nst -= PSTAGES;
            load_stage(nst, ks + 3);
        }
        CP_ASYNC_COMMIT();                 // empty group near the end keeps math
        CP_ASYNC_WAIT3();                  // stage ks resident
        __syncthreads();

        const uint16_t* A  = psm + st * P_STG_USH;
        const uint16_t* Bm = A + P_A_USH;

        #pragma unroll
        for (int kh = 0; kh < 2; kh++) {
            const int ko = kh * 16;
            uint32_t a[4][4], b[4][2];
            #pragma unroll
            for (int mf = 0; mf < 4; mf++) {
                uint32_t ad = (uint32_t)__cvta_generic_to_shared(
                    &A[(wm * 64 + mf * 16 + lrow8) * PROW + ko + lcol8]);
                ldmatrix_x4(a[mf][0], a[mf][1], a[mf][2], a[mf][3], ad);
            }
            #pragma unroll
            for (int np = 0; np < 2; np++) {
                uint32_t bd = (uint32_t)__cvta_generic_to_shared(
                    &Bm[(wn * 32 + np * 16 + lrow8) * PROW + ko + lcol8]);
                uint32_t b0, b1, b2, b3;
                ldmatrix_x4(b0, b1, b2, b3, bd);
                b[2 * np][0] = b0; b[2 * np][1] = b2;
                b[2 * np + 1][0] = b1; b[2 * np + 1][1] = b3;
            }
            #pragma unroll
            for (int mf = 0; mf < 4; mf++)
                #pragma unroll
                for (int nf = 0; nf < 4; nf++)
                    mma_f16(acc[mf][nf], a[mf][0], a[mf][1], a[mf][2], a[mf][3],
                            b[nf][0], b[nf][1]);
        }
        __syncthreads();                   // stage st consumed; safe to refill
        if (++st >= PSTAGES) st = 0;
    }

    // Epilogue: bias add (+ Q pre-scale), store fp16 head-major.
    #pragma unroll
    for (int mf = 0; mf < 4; mf++) {
        int row = m0 + wm * 64 + mf * 16 + lr;
        #pragma unroll
        for (int nf = 0; nf < 4; nf++) {
            int col = n0 + wn * 32 + nf * 8 + lc * 2;
            float2 bv2 = *(const float2*)&bias[col];
            float v00 = (acc[mf][nf][0] + bv2.x) * oscale;
            float v01 = (acc[mf][nf][1] + bv2.y) * oscale;
            float v10 = (acc[mf][nf][2] + bv2.x) * oscale;
            float v11 = (acc[mf][nf][3] + bv2.y) * oscale;
            *(uint32_t*)&Out[QKV_IDX(row, col)]     = packhf(v00, v01);
            *(uint32_t*)&Out[QKV_IDX(row + 8, col)] = packhf(v10, v11);
        }
    }
}

// ---------------------------------------------------------------------------
// Flash attention, single-pass fp16 MMA, exp2-domain softmax (Q pre-scaled).
// (unchanged from R14)
// ---------------------------------------------------------------------------
#define RSTR 72                       // row stride in ushorts (144B)
#define SM_Q  0
#define SM_KV 18432                   // 2 stages of {K, V}
#define KV_STAGE 18432
#define OFF_K 0
#define OFF_V 9216
#define SM_MK (SM_KV + 2 * KV_STAGE)  // 55296; 2 x 256B mask stages
#define ATTN_SMEM (SM_MK + 512)       // 55808

__global__ __launch_bounds__(256, 2)
void attn_mma(const int* __restrict__ mask, float* __restrict__ out) {
    extern __shared__ char sm[];

    const int qb = (int)(gridDim.x - 1) - (int)blockIdx.x;   // heavy blocks first
    const int h  = blockIdx.y;
    const int b  = blockIdx.z;
    const int q0 = qb * 128;
    const int t  = threadIdx.x;
    const int w  = t >> 5;
    const int lid = t & 31;
    const int lr = lid >> 2;
    const int lc = lid & 3;

    const size_t hb = ((size_t)(b * H_ + h)) << 16;
    const uint16_t* Qg = g_Q16 + hb;
    const uint16_t* Kg = g_K16 + hb;
    const uint16_t* Vg = g_V16 + hb;
    const int* mrow = mask + b * S_;
    const int* mflag = g_mflag + b * (S_ / 64);

    const uint32_t smb = (uint32_t)__cvta_generic_to_shared(sm);
    const int lrow8 = (lid & 7) + (lid & 8);
    const int lcol8 = (lid >> 4) << 3;

    {
        int row = t >> 1, half = (t & 1) * 32;
        size_t g = ((size_t)(q0 + row) << 6) + half;
        uint32_t so = (uint32_t)(row * RSTR + half) * 2;
        #pragma unroll
        for (int i = 0; i < 4; i++)
            cp_async16(sm + SM_Q + so + i * 16, Qg + g + i * 8);
    }
    CP_ASYNC_COMMIT();

    auto load_kv = [&](int st, int kt) {
        int r = t >> 2, seg = t & 3;
        size_t g = ((size_t)(kt * 64 + r) << 6) + seg * 16;
        char* stb = sm + SM_KV + st * KV_STAGE;
        uint32_t so = (uint32_t)(r * RSTR + seg * 16) * 2;
        cp_async16(stb + OFF_K + so,      Kg + g);
        cp_async16(stb + OFF_K + so + 16, Kg + g + 8);
        cp_async16(stb + OFF_V + so,      Vg + g);
        cp_async16(stb + OFF_V + so + 16, Vg + g + 8);
        if (t < 16)
            cp_async16(sm + SM_MK + st * 256 + t * 16, mrow + kt * 64 + t * 4);
    };

    load_kv(0, 0);
    CP_ASYNC_COMMIT();

    float o[8][4];
    #pragma unroll
    for (int i = 0; i < 8; i++)
        #pragma unroll
        for (int j = 0; j < 4; j++) o[i][j] = 0.f;
    float m0 = -1.0e30f, m1 = -1.0e30f, l0 = 0.f, l1 = 0.f;

    const int gr0 = q0 + w * 16 + lr;
    const int ntiles = 2 * qb + 2;

    for (int kt = 0; kt < ntiles; kt++) {
        const int st = kt & 1;
        if (kt + 1 < ntiles) load_kv(st ^ 1, kt + 1);
        CP_ASYNC_COMMIT();
        CP_ASYNC_WAIT1();
        __syncthreads();

        const bool active = (kt * 64 <= q0 + w * 16 + 15);
        if (active) {
            const uint32_t k32 = smb + SM_KV + st * KV_STAGE + OFF_K;
            const uint32_t v32 = smb + SM_KV + st * KV_STAGE + OFF_V;
            const int* mk = (const int*)(sm + SM_MK + st * 256);

            int rem = q0 + w * 16 + 15 - kt * 64;
            if (rem > 63) rem = 63;
            const int nlim = (rem >> 4) + 1;          // 1..4

            float s[8][4];
            #pragma unroll
            for (int i = 0; i < 8; i++)
                #pragma unroll
                for (int j = 0; j < 4; j++) s[i][j] = 0.f;

            #pragma unroll
            for (int ks = 0; ks < 4; ks++) {
                const int ko = ks * 16;
                const uint32_t afo =
                    (uint32_t)((w * 16 + lrow8) * RSTR + ko + lcol8) * 2;
                uint32_t a0, a1, a2, a3;
                ldmatrix_x4(a0, a1, a2, a3, smb + SM_Q + afo);
                #pragma unroll
                for (int nfp = 0; nfp < 4; nfp++) {
                    if (nfp < nlim) {
                        const uint32_t bfo =
                            (uint32_t)((nfp * 16 + lrow8) * RSTR + ko + lcol8) * 2;
                        uint32_t b0, b1, b2, b3;
                        ldmatrix_x4(b0, b1, b2, b3, k32 + bfo);
                        mma_f16(s[2*nfp],   a0, a1, a2, a3, b0, b2);
                        mma_f16(s[2*nfp+1], a0, a1, a2, a3, b1, b3);
                    }
                }
            }

            const bool diag = (kt >= 2 * qb);
            const int  fl   = mflag[kt];
            if (diag | !fl) {
                if (fl) {
                    #pragma unroll
                    for (int nf = 0; nf < 8; nf++) {
                        int c0 = kt * 64 + nf * 8 + 2 * lc, c1 = c0 + 1;
                        if (c0 > gr0)     s[nf][0] = -1.0e30f;
                        if (c1 > gr0)     s[nf][1] = -1.0e30f;
                        if (c0 > gr0 + 8) s[nf][2] = -1.0e30f;
                        if (c1 > gr0 + 8) s[nf][3] = -1.0e30f;
                    }
                } else {
                    #pragma unroll
                    for (int nf = 0; nf < 8; nf++) {
                        int ci = nf * 8 + 2 * lc;
                        int c0 = kt * 64 + ci, c1 = c0 + 1;
                        int mv0 = mk[ci], mv1 = mk[ci + 1];
                        if ((diag && c0 > gr0) || mv0 == 0)     s[nf][0] = -1.0e30f;
                        if ((diag && c1 > gr0) || mv1 == 0)     s[nf][1] = -1.0e30f;
                        if ((diag && c0 > gr0 + 8) || mv0 == 0) s[nf][2] = -1.0e30f;
                        if ((diag && c1 > gr0 + 8) || mv1 == 0) s[nf][3] = -1.0e30f;
                    }
                }
            }

            float mx0 = -1.0e30f, mx1 = -1.0e30f;
            #pragma unroll
            for (int nf = 0; nf < 8; nf++) {
                mx0 = fmaxf(mx0, fmaxf(s[nf][0], s[nf][1]));
                mx1 = fmaxf(mx1, fmaxf(s[nf][2], s[nf][3]));
            }
            mx0 = fmaxf(mx0, __shfl_xor_sync(0xffffffffu, mx0, 1));
            mx0 = fmaxf(mx0, __shfl_xor_sync(0xffffffffu, mx0, 2));
            mx1 = fmaxf(mx1, __shfl_xor_sync(0xffffffffu, mx1, 1));
            mx1 = fmaxf(mx1, __shfl_xor_sync(0xffffffffu, mx1, 2));
            float mn0 = fmaxf(m0, mx0), mn1 = fmaxf(m1, mx1);
            float alpha0 = exp2f(m0 - mn0), alpha1 = exp2f(m1 - mn1);
            m0 = mn0; m1 = mn1;

            float sum0 = 0.f, sum1 = 0.f;
            #pragma unroll
            for (int nf = 0; nf < 8; nf++) {
                float p;
                p = exp2f(s[nf][0] - mn0); s[nf][0] = p; sum0 += p;
                p = exp2f(s[nf][1] - mn0); s[nf][1] = p; sum0 += p;
                p = exp2f(s[nf][2] - mn1); s[nf][2] = p; sum1 += p;
                p = exp2f(s[nf][3] - mn1); s[nf][3] = p; sum1 += p;
            }
            sum0 += __shfl_xor_sync(0xffffffffu, sum0, 1);
            sum0 += __shfl_xor_sync(0xffffffffu, sum0, 2);
            sum1 += __shfl_xor_sync(0xffffffffu, sum1, 1);
            sum1 += __shfl_xor_sync(0xffffffffu, sum1, 2);
            l0 = l0 * alpha0 + sum0;
            l1 = l1 * alpha1 + sum1;

            #pragma unroll
            for (int nf = 0; nf < 8; nf++) {
                o[nf][0] *= alpha0; o[nf][1] *= alpha0;
                o[nf][2] *= alpha1; o[nf][3] *= alpha1;
            }

            const int g  = lid >> 3;
            const int lrow = lid & 7;
            #pragma unroll
            for (int ks = 0; ks < 4; ks++) {
                if (ks < nlim) {
                    uint32_t p0 = packhf(s[2*ks][0],   s[2*ks][1]);
                    uint32_t p1 = packhf(s[2*ks][2],   s[2*ks][3]);
                    uint32_t p2 = packhf(s[2*ks+1][0], s[2*ks+1][1]);
                    uint32_t p3 = packhf(s[2*ks+1][2], s[2*ks+1][3]);
                    #pragma unroll
                    for (int nfp = 0; nfp < 4; nfp++) {
                        uint32_t offB = (uint32_t)((ks * 16 + (g & 1) * 8 + lrow) * RSTR
                                                   + nfp * 16 + (g >> 1) * 8) * 2;
                        uint32_t b0, b1, b2, b3;
                        ldmatrix_x4_trans(b0, b1, b2, b3, v32 + offB);
                        mma_f16(o[2*nfp],   p0, p1, p2, p3, b0, b1);
                        mma_f16(o[2*nfp+1], p0, p1, p2, p3, b2, b3);
                    }
                }
            }
        }
        __syncthreads();
    }

    float inv0 = 1.0f / l0, inv1 = 1.0f / l1;
    #pragma unroll
    for (int nf = 0; nf < 8; nf++) {
        int col = h * DK_ + nf * 8 + 2 * lc;
        float2 r0, r1;
        r0.x = o[nf][0] * inv0; r0.y = o[nf][1] * inv0;
        r1.x = o[nf][2] * inv1; r1.y = o[nf][3] * inv1;
        *(float2*)&out[(size_t)(b * S_ + gr0) * D_ + col] = r0;
        *(float2*)&out[(size_t)(b * S_ + gr0 + 8) * D_ + col] = r1;
    }
}

// ---------------------------------------------------------------------------
// Launch
// inputs: query, key, value, att_mask, Wq, bq, Wk, bk, Wv, bv
// ---------------------------------------------------------------------------
extern "C" void kernel_launch(void* const* d_in, const int* in_sizes, int n_in,
                              void* d_out, int out_size) {
    (void)in_sizes; (void)n_in; (void)out_size;
    const float* query = (const float*)d_in[0];
    const float* key   = (const float*)d_in[1];
    const float* value = (const float*)d_in[2];
    const int*   amask = (const int*)  d_in[3];
    const float* Wq = (const float*)d_in[4];
    const float* bq = (const float*)d_in[5];
    const float* Wk = (const float*)d_in[6];
    const float* bk = (const float*)d_in[7];
    const float* Wv = (const float*)d_in[8];
    const float* bv = (const float*)d_in[9];
    float* out = (float*)d_out;

    static uint16_t *x16 = nullptr, *w16 = nullptr;
    if (!x16) {
        cudaGetSymbolAddress((void**)&x16, g_X16);
        cudaGetSymbolAddress((void**)&w16, g_W16);
        cudaFuncSetAttribute(qkv_proj_mma,
                             cudaFuncAttributeMaxDynamicSharedMemorySize, PROJ_SMEM);
        cudaFuncSetAttribute(attn_mma,
                             cudaFuncAttributeMaxDynamicSharedMemorySize, ATTN_SMEM);
    }

    const int NX4 = M_TOT * D_ / 4;   // 1048576
    const int NW4 = D_ * D_ / 4;      // 262144
    dim3 gx((NX4 + 255) / 256, 1, 3);
    cvt_f16_kernel<<<gx, 256>>>(query, key, value, x16, NX4);
    dim3 gw((NW4 + 255) / 256, 1, 3);
    cvt_f16_kernel<<<gw, 256>>>(Wq, Wk, Wv, w16, NW4);
    mask_flags_kernel<<<1, 64>>>(amask);

    dim3 gproj(D_ / PBN, M_TOT / PBM, 3);   // (8, 32, 3)
    qkv_proj_mma<<<gproj, 256, PROJ_SMEM>>>(bq, bk, bv);

    dim3 gattn(S_ / 128, H_, B_);            // (8, 16, 4)
    attn_mma<<<gattn, 256, ATTN_SMEM>>>(amask, out);
}

// round 16
// speedup vs baseline: 1.0863x; 1.0863x over previous
#include <cuda_runtime.h>
#include <cuda_bf16.h>
#include <cuda_fp16.h>
#include <cstdint>

// Problem constants
#define B_ 4
#define S_ 1024
#define D_ 1024
#define H_ 16
#define DK_ 64
#define M_TOT (B_ * S_)   // 4096

// Q/K/V in fp16, head-major: [(b*H+h)][s][64], 64-elem rows (128B).
// Q is pre-scaled by 0.125*log2(e).
__device__ uint16_t g_Q16[B_ * H_ * S_ * DK_];
__device__ uint16_t g_K16[B_ * H_ * S_ * DK_];
__device__ uint16_t g_V16[B_ * H_ * S_ * DK_];
// fp16-pre-converted projection inputs
__device__ uint16_t g_X16[3 * M_TOT * D_];
__device__ uint16_t g_W16[3 * D_ * D_];
// per-64-column-block mask validity flags: [b][blk] (1 = all 64 cols valid)
__device__ int g_mflag[B_ * (S_ / 64)];

#define SCL_Q 0.18033688011112042f   // 0.125 * log2(e)

// ---------------------------------------------------------------------------
// PTX helpers (baseline sm_80+ features only — target is sm_100 BASE).
// ---------------------------------------------------------------------------
__device__ __forceinline__ void cp_async16(void* smem_dst, const void* gmem_src) {
    uint32_t d = (uint32_t)__cvta_generic_to_shared(smem_dst);
    asm volatile("cp.async.ca.shared.global [%0], [%1], 16;"
                 :: "r"(d), "l"(gmem_src) : "memory");
}
#define CP_ASYNC_COMMIT() asm volatile("cp.async.commit_group;" ::: "memory")
#define CP_ASYNC_WAIT0()  asm volatile("cp.async.wait_group 0;" ::: "memory")
#define CP_ASYNC_WAIT1()  asm volatile("cp.async.wait_group 1;" ::: "memory")

// fp16 m16n8k16, fp32 accumulate
__device__ __forceinline__ void mma_f16(float c[4],
                                        uint32_t a0, uint32_t a1, uint32_t a2, uint32_t a3,
                                        uint32_t b0, uint32_t b1) {
    asm volatile(
        "mma.sync.aligned.m16n8k16.row.col.f32.f16.f16.f32 "
        "{%0,%1,%2,%3}, {%4,%5,%6,%7}, {%8,%9}, {%0,%1,%2,%3};"
        : "+f"(c[0]), "+f"(c[1]), "+f"(c[2]), "+f"(c[3])
        : "r"(a0), "r"(a1), "r"(a2), "r"(a3), "r"(b0), "r"(b1));
}
__device__ __forceinline__ void ldmatrix_x4(uint32_t& r0, uint32_t& r1,
                                            uint32_t& r2, uint32_t& r3,
                                            uint32_t smem_addr) {
    asm volatile("ldmatrix.sync.aligned.m8n8.x4.shared.b16 "
                 "{%0,%1,%2,%3}, [%4];"
                 : "=r"(r0), "=r"(r1), "=r"(r2), "=r"(r3) : "r"(smem_addr));
}
__device__ __forceinline__ void ldmatrix_x4_trans(uint32_t& r0, uint32_t& r1,
                                                  uint32_t& r2, uint32_t& r3,
                                                  uint32_t smem_addr) {
    asm volatile("ldmatrix.sync.aligned.m8n8.x4.trans.shared.b16 "
                 "{%0,%1,%2,%3}, [%4];"
                 : "=r"(r0), "=r"(r1), "=r"(r2), "=r"(r3) : "r"(smem_addr));
}
__device__ __forceinline__ uint32_t packhf(float a, float b) {
    __half2 t = __floats2half2_rn(a, b);
    return *reinterpret_cast<uint32_t*>(&t);
}

// head-major index for proj epilogue stores
#define QKV_IDX(row, col) \
    ((((size_t)((row) >> 10) * H_ + ((col) >> 6)) << 16) + \
     (((size_t)((row) & 1023)) << 6) + ((col) & 63))

// ---------------------------------------------------------------------------
// Pre-pass: fp32 -> fp16, float4-vectorized, z picks tensor.
// ---------------------------------------------------------------------------
__global__ void cvt_f16_kernel(const float* __restrict__ a,
                               const float* __restrict__ b,
                               const float* __restrict__ c,
                               uint16_t* __restrict__ out, int n4) {
    int i = blockIdx.x * blockDim.x + threadIdx.x;
    if (i >= n4) return;
    const float* src = (blockIdx.z == 0) ? a : (blockIdx.z == 1) ? b : c;
    float4 v = ((const float4*)src)[i];
    uint2 r;
    r.x = packhf(v.x, v.y);
    r.y = packhf(v.z, v.w);
    ((uint2*)(out + (size_t)blockIdx.z * n4 * 4))[i] = r;
}

// ---------------------------------------------------------------------------
// Pre-pass: mask -> per-64-col-block validity flag. One thread per block.
// ---------------------------------------------------------------------------
__global__ void mask_flags_kernel(const int* __restrict__ mask) {
    int i = threadIdx.x;                 // 0..63  -> (b, blk)
    if (i >= B_ * (S_ / 64)) return;
    const int* m = mask + (i >> 4) * S_ + (i & 15) * 64;
    int all = 1;
    #pragma unroll 8
    for (int j = 0; j < 64; j++) all &= (m[j] != 0);
    g_mflag[i] = all;
}

// ---------------------------------------------------------------------------
// Projection GEMM via fp16 m16n8k16. PBK=64, 2-stage, ONE barrier per k-step:
//   wait(fill ks) -> bar -> fill ks+1 -> commit -> 64 mma/warp
// The bar proves all warps finished reading the stage being refilled.
// Epilogue emits fp16 head-major; Q output pre-scaled by SCL_Q.
// ---------------------------------------------------------------------------
#define PBM 128
#define PBN 128
#define PBK 64
#define PROW 72                     // ushort row stride (144B) — conflict-free
#define KSTEPS (D_ / PBK)           // 16
#define P_A_USH (PBM * PROW)        // 9216 ushorts per A tile
#define P_STG_USH (2 * P_A_USH)     // A then B per stage
#define PROJ_SMEM (2 * P_STG_USH * 2)   // 73728 B

__global__ __launch_bounds__(256, 2)
void qkv_proj_mma(const float* __restrict__ bq,
                  const float* __restrict__ bk,
                  const float* __restrict__ bv) {
    extern __shared__ uint16_t psm[];

    const int z = blockIdx.z;
    const uint16_t* X = g_X16 + (size_t)z * M_TOT * D_;
    const uint16_t* W = g_W16 + (size_t)z * D_ * D_;
    const float* bias = (z == 0) ? bq : (z == 1) ? bk : bv;
    uint16_t* Out = (z == 0) ? g_Q16 : (z == 1) ? g_K16 : g_V16;
    const float oscale = (z == 0) ? SCL_Q : 1.0f;

    const int t   = threadIdx.x;
    const int wid = t >> 5;
    const int lid = t & 31;
    const int lr  = lid >> 2;
    const int lc  = lid & 3;
    const int wm  = wid & 1;
    const int wn  = wid >> 1;
    const int m0  = blockIdx.y * PBM;
    const int n0  = blockIdx.x * PBN;

    const int lrow8 = (lid & 7) + (lid & 8);          // 0..15
    const int lcol8 = (lid >> 4) << 3;                // 0 or 8

    float acc[4][4][4];
    #pragma unroll
    for (int i = 0; i < 4; i++)
        #pragma unroll
        for (int j = 0; j < 4; j++)
            #pragma unroll
            for (int r = 0; r < 4; r++) acc[i][j][r] = 0.f;

    // Fill one stage: 128 rows x 8 16B-chunks per matrix = 1024 jobs each;
    // 4 A-jobs + 4 B-jobs per thread.
    auto load_stage = [&](int st, int ks) {
        const int k0 = ks * PBK;
        uint16_t* A  = psm + st * P_STG_USH;
        uint16_t* Bm = A + P_A_USH;
        #pragma unroll
        for (int i = 0; i < 4; i++) {
            int job = t + i * 256;          // 0..1023
            int row = job >> 3;             // 0..127
            int ch  = (job & 7) * 8;        // ushort offset 0..56
            cp_async16(&A[row * PROW + ch],  &X[(size_t)(m0 + row) * D_ + k0 + ch]);
            cp_async16(&Bm[row * PROW + ch], &W[(size_t)(n0 + row) * D_ + k0 + ch]);
        }
    };

    load_stage(0, 0);
    CP_ASYNC_COMMIT();

    for (int ks = 0; ks < KSTEPS; ks++) {
        const int s = ks & 1;
        CP_ASYNC_WAIT0();                  // stage ks resident
        __syncthreads();                   // everyone done reading stage s^1
        if (ks + 1 < KSTEPS) {
            load_stage(s ^ 1, ks + 1);     // safe: bar proved reads complete
            CP_ASYNC_COMMIT();
        }

        const uint16_t* A  = psm + s * P_STG_USH;
        const uint16_t* Bm = A + P_A_USH;

        #pragma unroll
        for (int kh = 0; kh < 4; kh++) {              // four k16 halves
            const int ko = kh * 16;
            uint32_t a[4][4], b[4][2];
            #pragma unroll
            for (int mf = 0; mf < 4; mf++) {
                uint32_t ad = (uint32_t)__cvta_generic_to_shared(
                    &A[(wm * 64 + mf * 16 + lrow8) * PROW + ko + lcol8]);
                ldmatrix_x4(a[mf][0], a[mf][1], a[mf][2], a[mf][3], ad);
            }
            #pragma unroll
            for (int np = 0; np < 2; np++) {
                uint32_t bd = (uint32_t)__cvta_generic_to_shared(
                    &Bm[(wn * 32 + np * 16 + lrow8) * PROW + ko + lcol8]);
                uint32_t b0, b1, b2, b3;
                ldmatrix_x4(b0, b1, b2, b3, bd);
                b[2 * np][0] = b0; b[2 * np][1] = b2;
                b[2 * np + 1][0] = b1; b[2 * np + 1][1] = b3;
            }
            #pragma unroll
            for (int mf = 0; mf < 4; mf++)
                #pragma unroll
                for (int nf = 0; nf < 4; nf++)
                    mma_f16(acc[mf][nf], a[mf][0], a[mf][1], a[mf][2], a[mf][3],
                            b[nf][0], b[nf][1]);
        }
        // no trailing barrier: next iteration's leading bar covers the hazard
    }

    // Epilogue: bias add (+ Q pre-scale), store fp16 head-major.
    #pragma unroll
    for (int mf = 0; mf < 4; mf++) {
        int row = m0 + wm * 64 + mf * 16 + lr;
        #pragma unroll
        for (int nf = 0; nf < 4; nf++) {
            int col = n0 + wn * 32 + nf * 8 + lc * 2;
            float2 bv2 = *(const float2*)&bias[col];
            float v00 = (acc[mf][nf][0] + bv2.x) * oscale;
            float v01 = (acc[mf][nf][1] + bv2.y) * oscale;
            float v10 = (acc[mf][nf][2] + bv2.x) * oscale;
            float v11 = (acc[mf][nf][3] + bv2.y) * oscale;
            *(uint32_t*)&Out[QKV_IDX(row, col)]     = packhf(v00, v01);
            *(uint32_t*)&Out[QKV_IDX(row + 8, col)] = packhf(v10, v11);
        }
    }
}

// ---------------------------------------------------------------------------
// Flash attention, single-pass fp16 MMA, exp2-domain softmax (Q pre-scaled).
// (unchanged from R14)
// ---------------------------------------------------------------------------
#define RSTR 72                       // row stride in ushorts (144B)
#define SM_Q  0
#define SM_KV 18432                   // 2 stages of {K, V}
#define KV_STAGE 18432
#define OFF_K 0
#define OFF_V 9216
#define SM_MK (SM_KV + 2 * KV_STAGE)  // 55296; 2 x 256B mask stages
#define ATTN_SMEM (SM_MK + 512)       // 55808

__global__ __launch_bounds__(256, 2)
void attn_mma(const int* __restrict__ mask, float* __restrict__ out) {
    extern __shared__ char sm[];

    const int qb = (int)(gridDim.x - 1) - (int)blockIdx.x;   // heavy blocks first
    const int h  = blockIdx.y;
    const int b  = blockIdx.z;
    const int q0 = qb * 128;
    const int t  = threadIdx.x;
    const int w  = t >> 5;
    const int lid = t & 31;
    const int lr = lid >> 2;
    const int lc = lid & 3;

    const size_t hb = ((size_t)(b * H_ + h)) << 16;
    const uint16_t* Qg = g_Q16 + hb;
    const uint16_t* Kg = g_K16 + hb;
    const uint16_t* Vg = g_V16 + hb;
    const int* mrow = mask + b * S_;
    const int* mflag = g_mflag + b * (S_ / 64);

    const uint32_t smb = (uint32_t)__cvta_generic_to_shared(sm);
    const int lrow8 = (lid & 7) + (lid & 8);
    const int lcol8 = (lid >> 4) << 3;

    {
        int row = t >> 1, half = (t & 1) * 32;
        size_t g = ((size_t)(q0 + row) << 6) + half;
        uint32_t so = (uint32_t)(row * RSTR + half) * 2;
        #pragma unroll
        for (int i = 0; i < 4; i++)
            cp_async16(sm + SM_Q + so + i * 16, Qg + g + i * 8);
    }
    CP_ASYNC_COMMIT();

    auto load_kv = [&](int st, int kt) {
        int r = t >> 2, seg = t & 3;
        size_t g = ((size_t)(kt * 64 + r) << 6) + seg * 16;
        char* stb = sm + SM_KV + st * KV_STAGE;
        uint32_t so = (uint32_t)(r * RSTR + seg * 16) * 2;
        cp_async16(stb + OFF_K + so,      Kg + g);
        cp_async16(stb + OFF_K + so + 16, Kg + g + 8);
        cp_async16(stb + OFF_V + so,      Vg + g);
        cp_async16(stb + OFF_V + so + 16, Vg + g + 8);
        if (t < 16)
            cp_async16(sm + SM_MK + st * 256 + t * 16, mrow + kt * 64 + t * 4);
    };

    load_kv(0, 0);
    CP_ASYNC_COMMIT();

    float o[8][4];
    #pragma unroll
    for (int i = 0; i < 8; i++)
        #pragma unroll
        for (int j = 0; j < 4; j++) o[i][j] = 0.f;
    float m0 = -1.0e30f, m1 = -1.0e30f, l0 = 0.f, l1 = 0.f;

    const int gr0 = q0 + w * 16 + lr;
    const int ntiles = 2 * qb + 2;

    for (int kt = 0; kt < ntiles; kt++) {
        const int st = kt & 1;
        if (kt + 1 < ntiles) load_kv(st ^ 1, kt + 1);
        CP_ASYNC_COMMIT();
        CP_ASYNC_WAIT1();
        __syncthreads();

        const bool active = (kt * 64 <= q0 + w * 16 + 15);
        if (active) {
            const uint32_t k32 = smb + SM_KV + st * KV_STAGE + OFF_K;
            const uint32_t v32 = smb + SM_KV + st * KV_STAGE + OFF_V;
            const int* mk = (const int*)(sm + SM_MK + st * 256);

            int rem = q0 + w * 16 + 15 - kt * 64;
            if (rem > 63) rem = 63;
            const int nlim = (rem >> 4) + 1;          // 1..4

            float s[8][4];
            #pragma unroll
            for (int i = 0; i < 8; i++)
                #pragma unroll
                for (int j = 0; j < 4; j++) s[i][j] = 0.f;

            #pragma unroll
            for (int ks = 0; ks < 4; ks++) {
                const int ko = ks * 16;
                const uint32_t afo =
                    (uint32_t)((w * 16 + lrow8) * RSTR + ko + lcol8) * 2;
                uint32_t a0, a1, a2, a3;
                ldmatrix_x4(a0, a1, a2, a3, smb + SM_Q + afo);
                #pragma unroll
                for (int nfp = 0; nfp < 4; nfp++) {
                    if (nfp < nlim) {
                        const uint32_t bfo =
                            (uint32_t)((nfp * 16 + lrow8) * RSTR + ko + lcol8) * 2;
                        uint32_t b0, b1, b2, b3;
                        ldmatrix_x4(b0, b1, b2, b3, k32 + bfo);
                        mma_f16(s[2*nfp],   a0, a1, a2, a3, b0, b2);
                        mma_f16(s[2*nfp+1], a0, a1, a2, a3, b1, b3);
                    }
                }
            }

            const bool diag = (kt >= 2 * qb);
            const int  fl   = mflag[kt];
            if (diag | !fl) {
                if (fl) {
                    #pragma unroll
                    for (int nf = 0; nf < 8; nf++) {
                        int c0 = kt * 64 + nf * 8 + 2 * lc, c1 = c0 + 1;
                        if (c0 > gr0)     s[nf][0] = -1.0e30f;
                        if (c1 > gr0)     s[nf][1] = -1.0e30f;
                        if (c0 > gr0 + 8) s[nf][2] = -1.0e30f;
                        if (c1 > gr0 + 8) s[nf][3] = -1.0e30f;
                    }
                } else {
                    #pragma unroll
                    for (int nf = 0; nf < 8; nf++) {
                        int ci = nf * 8 + 2 * lc;
                        int c0 = kt * 64 + ci, c1 = c0 + 1;
                        int mv0 = mk[ci], mv1 = mk[ci + 1];
                        if ((diag && c0 > gr0) || mv0 == 0)     s[nf][0] = -1.0e30f;
                        if ((diag && c1 > gr0) || mv1 == 0)     s[nf][1] = -1.0e30f;
                        if ((diag && c0 > gr0 + 8) || mv0 == 0) s[nf][2] = -1.0e30f;
                        if ((diag && c1 > gr0 + 8) || mv1 == 0) s[nf][3] = -1.0e30f;
                    }
                }
            }

            float mx0 = -1.0e30f, mx1 = -1.0e30f;
            #pragma unroll
            for (int nf = 0; nf < 8; nf++) {
                mx0 = fmaxf(mx0, fmaxf(s[nf][0], s[nf][1]));
                mx1 = fmaxf(mx1, fmaxf(s[nf][2], s[nf][3]));
            }
            mx0 = fmaxf(mx0, __shfl_xor_sync(0xffffffffu, mx0, 1));
            mx0 = fmaxf(mx0, __shfl_xor_sync(0xffffffffu, mx0, 2));
            mx1 = fmaxf(mx1, __shfl_xor_sync(0xffffffffu, mx1, 1));
            mx1 = fmaxf(mx1, __shfl_xor_sync(0xffffffffu, mx1, 2));
            float mn0 = fmaxf(m0, mx0), mn1 = fmaxf(m1, mx1);
            float alpha0 = exp2f(m0 - mn0), alpha1 = exp2f(m1 - mn1);
            m0 = mn0; m1 = mn1;

            float sum0 = 0.f, sum1 = 0.f;
            #pragma unroll
            for (int nf = 0; nf < 8; nf++) {
                float p;
                p = exp2f(s[nf][0] - mn0); s[nf][0] = p; sum0 += p;
                p = exp2f(s[nf][1] - mn0); s[nf][1] = p; sum0 += p;
                p = exp2f(s[nf][2] - mn1); s[nf][2] = p; sum1 += p;
                p = exp2f(s[nf][3] - mn1); s[nf][3] = p; sum1 += p;
            }
            sum0 += __shfl_xor_sync(0xffffffffu, sum0, 1);
            sum0 += __shfl_xor_sync(0xffffffffu, sum0, 2);
            sum1 += __shfl_xor_sync(0xffffffffu, sum1, 1);
            sum1 += __shfl_xor_sync(0xffffffffu, sum1, 2);
            l0 = l0 * alpha0 + sum0;
            l1 = l1 * alpha1 + sum1;

            #pragma unroll
            for (int nf = 0; nf < 8; nf++) {
                o[nf][0] *= alpha0; o[nf][1] *= alpha0;
                o[nf][2] *= alpha1; o[nf][3] *= alpha1;
            }

            const int g  = lid >> 3;
            const int lrow = lid & 7;
            #pragma unroll
            for (int ks = 0; ks < 4; ks++) {
                if (ks < nlim) {
                    uint32_t p0 = packhf(s[2*ks][0],   s[2*ks][1]);
                    uint32_t p1 = packhf(s[2*ks][2],   s[2*ks][3]);
                    uint32_t p2 = packhf(s[2*ks+1][0], s[2*ks+1][1]);
                    uint32_t p3 = packhf(s[2*ks+1][2], s[2*ks+1][3]);
                    #pragma unroll
                    for (int nfp = 0; nfp < 4; nfp++) {
                        uint32_t offB = (uint32_t)((ks * 16 + (g & 1) * 8 + lrow) * RSTR
                                                   + nfp * 16 + (g >> 1) * 8) * 2;
                        uint32_t b0, b1, b2, b3;
                        ldmatrix_x4_trans(b0, b1, b2, b3, v32 + offB);
                        mma_f16(o[2*nfp],   p0, p1, p2, p3, b0, b1);
                        mma_f16(o[2*nfp+1], p0, p1, p2, p3, b2, b3);
                    }
                }
            }
        }
        __syncthreads();
    }

    float inv0 = 1.0f / l0, inv1 = 1.0f / l1;
    #pragma unroll
    for (int nf = 0; nf < 8; nf++) {
        int col = h * DK_ + nf * 8 + 2 * lc;
        float2 r0, r1;
        r0.x = o[nf][0] * inv0; r0.y = o[nf][1] * inv0;
        r1.x = o[nf][2] * inv1; r1.y = o[nf][3] * inv1;
        *(float2*)&out[(size_t)(b * S_ + gr0) * D_ + col] = r0;
        *(float2*)&out[(size_t)(b * S_ + gr0 + 8) * D_ + col] = r1;
    }
}

// ---------------------------------------------------------------------------
// Launch
// inputs: query, key, value, att_mask, Wq, bq, Wk, bk, Wv, bv
// ---------------------------------------------------------------------------
extern "C" void kernel_launch(void* const* d_in, const int* in_sizes, int n_in,
                              void* d_out, int out_size) {
    (void)in_sizes; (void)n_in; (void)out_size;
    const float* query = (const float*)d_in[0];
    const float* key   = (const float*)d_in[1];
    const float* value = (const float*)d_in[2];
    const int*   amask = (const int*)  d_in[3];
    const float* Wq = (const float*)d_in[4];
    const float* bq = (const float*)d_in[5];
    const float* Wk = (const float*)d_in[6];
    const float* bk = (const float*)d_in[7];
    const float* Wv = (const float*)d_in[8];
    const float* bv = (const float*)d_in[9];
    float* out = (float*)d_out;

    static uint16_t *x16 = nullptr, *w16 = nullptr;
    if (!x16) {
        cudaGetSymbolAddress((void**)&x16, g_X16);
        cudaGetSymbolAddress((void**)&w16, g_W16);
        cudaFuncSetAttribute(qkv_proj_mma,
                             cudaFuncAttributeMaxDynamicSharedMemorySize, PROJ_SMEM);
        cudaFuncSetAttribute(attn_mma,
                             cudaFuncAttributeMaxDynamicSharedMemorySize, ATTN_SMEM);
    }

    const int NX4 = M_TOT * D_ / 4;   // 1048576
    const int NW4 = D_ * D_ / 4;      // 262144
    dim3 gx((NX4 + 255) / 256, 1, 3);
    cvt_f16_kernel<<<gx, 256>>>(query, key, value, x16, NX4);
    dim3 gw((NW4 + 255) / 256, 1, 3);
    cvt_f16_kernel<<<gw, 256>>>(Wq, Wk, Wv, w16, NW4);
    mask_flags_kernel<<<1, 64>>>(amask);

    dim3 gproj(D_ / PBN, M_TOT / PBM, 3);   // (8, 32, 3)
    qkv_proj_mma<<<gproj, 256, PROJ_SMEM>>>(bq, bk, bv);

    dim3 gattn(S_ / 128, H_, B_);            // (8, 16, 4)
    attn_mma<<<gattn, 256, ATTN_SMEM>>>(amask, out);
}